// round 1
// baseline (speedup 1.0000x reference)
#include <cuda_runtime.h>
#include <math.h>

// ---------------- problem constants ----------------
#define BZ    8
#define HH    56
#define WW    56
#define HWP   3136        // 56*56
#define RR    25088       // BZ*HWP rows
#define C0N   256
#define C1N   512
#define C2N   1024
#define CIN   1794
#define KP    1808        // CIN padded to multiple of 16
#define DOUT  448
#define NC    3136        // number of centers

// ---------------- scratch (__device__ globals; no allocation allowed) ----------------
__device__ float g_pool1[BZ * C1N * 28 * 28];        // 12.8 MB
__device__ float g_pool2[BZ * C2N * 14 * 14];        //  6.4 MB
__device__ float g_X[(size_t)KP * RR];               // 181 MB, layout X[k][r] (k-major)
__device__ float g_Wp[KP * DOUT];                    // padded weights, Wp[k][o]
__device__ float g_phi[(size_t)RR * DOUT];           // 45 MB, row-major
__device__ float g_feat2[RR];
__device__ float g_cent2[NC];

// ---------------- helpers ----------------
__device__ __forceinline__ float bilin(const float* __restrict__ ch, int S, float u, float v) {
    int y0 = (int)floorf(u); float fy = u - (float)y0;
    int x0 = (int)floorf(v); float fx = v - (float)x0;
    int y0c = min(max(y0, 0), S - 1);
    int y1c = min(max(y0 + 1, 0), S - 1);
    int x0c = min(max(x0, 0), S - 1);
    int x1c = min(max(x0 + 1, 0), S - 1);
    float a = ch[y0c * S + x0c];
    float b = ch[y0c * S + x1c];
    float c = ch[y1c * S + x0c];
    float d = ch[y1c * S + x1c];
    return (1.f - fy) * ((1.f - fx) * a + fx * b) + fy * ((1.f - fx) * c + fx * d);
}

__device__ __forceinline__ void ins3(float v, float& a, float& b, float& c) {
    if (v < c) {
        if (v < b) {
            c = b;
            if (v < a) { b = a; a = v; } else { b = v; }
        } else {
            c = v;
        }
    }
}

// ---------------- stage 1: 3x3 avg pool (zero pad, /9) for p1 / p2 ----------------
__global__ void pool_kernel(const float* __restrict__ in, int total, int S, int which) {
    int idx = blockIdx.x * 256 + threadIdx.x;
    if (idx >= total) return;
    int x = idx % S;
    int y = (idx / S) % S;
    int bc = idx / (S * S);
    const float* p = in + (size_t)bc * S * S;
    float s = 0.f;
    #pragma unroll
    for (int dy = -1; dy <= 1; dy++) {
        int yy = y + dy;
        if ((unsigned)yy >= (unsigned)S) continue;
        #pragma unroll
        for (int dx = -1; dx <= 1; dx++) {
            int xx = x + dx;
            if ((unsigned)xx >= (unsigned)S) continue;
            s += p[yy * S + xx];
        }
    }
    float* out = which ? g_pool2 : g_pool1;
    out[idx] = s * (1.f / 9.f);
}

// ---------------- stage 2: pack weights (transpose + pad) ----------------
__global__ void prepw_kernel(const float* __restrict__ w) {
    int idx = blockIdx.x * 256 + threadIdx.x;
    if (idx >= KP * DOUT) return;
    int k = idx / DOUT;
    int o = idx % DOUT;
    g_Wp[idx] = (k < CIN) ? w[o * CIN + k] : 0.f;
}

// ---------------- stage 3: center norms ----------------
__global__ void cent2_kernel(const float* __restrict__ Cmat) {
    int n = blockIdx.x * 256 + threadIdx.x;
    if (n >= NC) return;
    float s = 0.f;
    for (int o = 0; o < DOUT; o++) {
        float v = Cmat[(size_t)o * NC + n];
        s += v * v;
    }
    g_cent2[n] = s;
}

// ---------------- stage 4: build X (k-major): pool p0 + bilinear levels + coords ----------------
__global__ void buildx_kernel(const float* __restrict__ p0) {
    int r = blockIdx.x * 256 + threadIdx.x;   // r < RR (RR % 256 == 0)
    int k = blockIdx.y;                       // 0..KP-1
    int b = r / HWP;
    int pix = r - b * HWP;
    int h = pix / WW;
    int w = pix - h * WW;
    float val;
    if (k < C0N) {
        const float* p = p0 + (size_t)(b * C0N + k) * HWP;
        float s = 0.f;
        #pragma unroll
        for (int dy = -1; dy <= 1; dy++) {
            int y = h + dy;
            if ((unsigned)y >= (unsigned)HH) continue;
            #pragma unroll
            for (int dx = -1; dx <= 1; dx++) {
                int x = w + dx;
                if ((unsigned)x >= (unsigned)WW) continue;
                s += p[y * WW + x];
            }
        }
        val = s * (1.f / 9.f);
    } else if (k < C0N + C1N) {
        const float* ch = g_pool1 + (size_t)(b * C1N + (k - C0N)) * 784;
        val = bilin(ch, 28, h * 0.5f - 0.25f, w * 0.5f - 0.25f);
    } else if (k < C0N + C1N + C2N) {
        const float* ch = g_pool2 + (size_t)(b * C2N + (k - C0N - C1N)) * 196;
        val = bilin(ch, 14, h * 0.25f - 0.375f, w * 0.25f - 0.375f);
    } else if (k == 1792) {
        val = (float)h * (2.f / 55.f) - 1.f;
    } else if (k == 1793) {
        val = (float)w * (2.f / 55.f) - 1.f;
    } else {
        val = 0.f;
    }
    g_X[(size_t)k * RR + r] = val;
}

// ---------------- stage 5: GEMM B  phi = X^T * Wp + bias ----------------
// X is k-major: X[k][r]. Tile: M=128 rows (r), N=64 (o), K-chunk 16.
__global__ void __launch_bounds__(256) gemmB_kernel(const float* __restrict__ bias) {
    __shared__ float As[16][128];
    __shared__ float Bs[16][64];
    int m0 = blockIdx.x * 128;
    int n0 = blockIdx.y * 64;
    int tid = threadIdx.x;
    int tx = tid & 15;       // column group (4 cols)
    int ty = tid >> 4;       // row group (8 rows)

    float acc[8][4];
    #pragma unroll
    for (int i = 0; i < 8; i++)
        #pragma unroll
        for (int j = 0; j < 4; j++) acc[i][j] = 0.f;

    for (int kc = 0; kc < KP; kc += 16) {
        #pragma unroll
        for (int it = 0; it < 2; it++) {
            int l = tid + it * 256;         // float4 index, 512 total
            int k = l >> 5;
            int m4 = (l & 31) << 2;
            float4 v = *(const float4*)(g_X + (size_t)(kc + k) * RR + m0 + m4);
            *(float4*)&As[k][m4] = v;
        }
        {
            int k = tid >> 4;
            int n4 = (tid & 15) << 2;
            float4 v = *(const float4*)(g_Wp + (kc + k) * DOUT + n0 + n4);
            *(float4*)&Bs[k][n4] = v;
        }
        __syncthreads();
        #pragma unroll
        for (int k = 0; k < 16; k++) {
            float4 a0 = *(const float4*)&As[k][ty * 8];
            float4 a1 = *(const float4*)&As[k][ty * 8 + 4];
            float4 bq = *(const float4*)&Bs[k][tx * 4];
            float av[8] = {a0.x, a0.y, a0.z, a0.w, a1.x, a1.y, a1.z, a1.w};
            float bv[4] = {bq.x, bq.y, bq.z, bq.w};
            #pragma unroll
            for (int i = 0; i < 8; i++)
                #pragma unroll
                for (int j = 0; j < 4; j++)
                    acc[i][j] = fmaf(av[i], bv[j], acc[i][j]);
        }
        __syncthreads();
    }

    float4 bb = *(const float4*)(bias + n0 + tx * 4);
    float bv[4] = {bb.x, bb.y, bb.z, bb.w};
    #pragma unroll
    for (int i = 0; i < 8; i++) {
        float4 o;
        o.x = acc[i][0] + bv[0];
        o.y = acc[i][1] + bv[1];
        o.z = acc[i][2] + bv[2];
        o.w = acc[i][3] + bv[3];
        *(float4*)(g_phi + (size_t)(m0 + ty * 8 + i) * DOUT + n0 + tx * 4) = o;
    }
}

// ---------------- stage 6: row norms of phi ----------------
__global__ void feat2_kernel() {
    int gw = (blockIdx.x * blockDim.x + threadIdx.x) >> 5;
    int lane = threadIdx.x & 31;
    if (gw >= RR) return;
    const float* row = g_phi + (size_t)gw * DOUT;
    float s = 0.f;
    for (int i = lane; i < DOUT; i += 32) {
        float v = row[i];
        s = fmaf(v, v, s);
    }
    #pragma unroll
    for (int o = 16; o; o >>= 1) s += __shfl_xor_sync(0xFFFFFFFFu, s, o);
    if (lane == 0) g_feat2[gw] = s;
}

// ---------------- stage 7: fused dist GEMM + top-3 + softmin score ----------------
// Block: 64 rows, loops 49 center tiles of 64, full phi row tile (448) in smem.
__global__ void __launch_bounds__(256, 1) gemmC_kernel(const float* __restrict__ Cmat,
                                                       float* __restrict__ out) {
    extern __shared__ float sm[];
    float* phiS = sm;                          // [448][68] (padded stride)
    float* CS   = sm + 448 * 68;               // [16][64]
    float* c2S  = CS + 16 * 64;                // [64]

    int r0 = blockIdx.x * 64;
    int tid = threadIdx.x;
    int tx = tid & 15;     // 4 centers
    int ty = tid >> 4;     // 4 rows

    // fill phiS transposed: phiS[k][m] = phi[r0+m][k]
    #pragma unroll 4
    for (int it = 0; it < 28; it++) {
        int l = tid + it * 256;         // float4 index, 64*112 total
        int m = l / 112;
        int k4 = (l - m * 112) * 4;
        float4 v = *(const float4*)(g_phi + (size_t)(r0 + m) * DOUT + k4);
        phiS[(k4 + 0) * 68 + m] = v.x;
        phiS[(k4 + 1) * 68 + m] = v.y;
        phiS[(k4 + 2) * 68 + m] = v.z;
        phiS[(k4 + 3) * 68 + m] = v.w;
    }

    const float BIG = 3.4e38f;
    float t0[4], t1[4], t2[4];
    #pragma unroll
    for (int i = 0; i < 4; i++) { t0[i] = BIG; t1[i] = BIG; t2[i] = BIG; }

    for (int n0 = 0; n0 < NC; n0 += 64) {
        __syncthreads();                         // protect c2S rewrite & phiS first use
        if (tid < 64) c2S[tid] = g_cent2[n0 + tid];

        float acc[4][4];
        #pragma unroll
        for (int i = 0; i < 4; i++)
            #pragma unroll
            for (int j = 0; j < 4; j++) acc[i][j] = 0.f;

        for (int kc = 0; kc < DOUT; kc += 16) {
            __syncthreads();
            {
                int k = tid >> 4;
                int n4 = (tid & 15) << 2;
                *(float4*)&CS[k * 64 + n4] =
                    *(const float4*)(Cmat + (size_t)(kc + k) * NC + n0 + n4);
            }
            __syncthreads();
            #pragma unroll
            for (int k = 0; k < 16; k++) {
                float4 a = *(const float4*)&phiS[(kc + k) * 68 + ty * 4];
                float4 bq = *(const float4*)&CS[k * 64 + tx * 4];
                float av[4] = {a.x, a.y, a.z, a.w};
                float bv[4] = {bq.x, bq.y, bq.z, bq.w};
                #pragma unroll
                for (int i = 0; i < 4; i++)
                    #pragma unroll
                    for (int j = 0; j < 4; j++)
                        acc[i][j] = fmaf(av[i], bv[j], acc[i][j]);
            }
        }

        // update per-thread top-3 by key = |c|^2 - 2*dot  (dist^2 = feat2 + key)
        #pragma unroll
        for (int i = 0; i < 4; i++) {
            #pragma unroll
            for (int j = 0; j < 4; j++) {
                float key = c2S[tx * 4 + j] - 2.f * acc[i][j];
                ins3(key, t0[i], t1[i], t2[i]);
            }
        }
    }

    __syncthreads();
    // merge: reuse phiS area as candidate buffer  cand[m][tx][3]
    float* cand = sm;
    #pragma unroll
    for (int i = 0; i < 4; i++) {
        int m = ty * 4 + i;
        cand[m * 48 + tx * 3 + 0] = t0[i];
        cand[m * 48 + tx * 3 + 1] = t1[i];
        cand[m * 48 + tx * 3 + 2] = t2[i];
    }
    __syncthreads();

    if (tid < 64) {
        int m = tid;
        float k0 = BIG, k1 = BIG, k2 = BIG;
        #pragma unroll 4
        for (int j = 0; j < 48; j++) {
            float v = cand[m * 48 + j];
            ins3(v, k0, k1, k2);
        }
        float f2 = g_feat2[r0 + m];
        float d0 = sqrtf(f2 + k0);
        float d1 = sqrtf(f2 + k1);
        float d2 = sqrtf(f2 + k2);
        float s = 1.f / (1.f + expf(d0 - d1) + expf(d0 - d2));   // softmin weight of d0
        out[r0 + m] = d0 * s;
    }
}

// ---------------- launch ----------------
extern "C" void kernel_launch(void* const* d_in, const int* in_sizes, int n_in,
                              void* d_out, int out_size) {
    (void)in_sizes; (void)n_in; (void)out_size;
    const float* p0     = (const float*)d_in[0];
    const float* p1     = (const float*)d_in[1];
    const float* p2     = (const float*)d_in[2];
    const float* conv_w = (const float*)d_in[3];
    const float* conv_b = (const float*)d_in[4];
    const float* Cmat   = (const float*)d_in[5];
    float* out = (float*)d_out;

    // 1) pools for levels 1, 2
    {
        int t1 = BZ * C1N * 28 * 28;
        pool_kernel<<<(t1 + 255) / 256, 256>>>(p1, t1, 28, 0);
        int t2 = BZ * C2N * 14 * 14;
        pool_kernel<<<(t2 + 255) / 256, 256>>>(p2, t2, 14, 1);
    }
    // 2) weight pack + center norms
    prepw_kernel<<<(KP * DOUT + 255) / 256, 256>>>(conv_w);
    cent2_kernel<<<(NC + 255) / 256, 256>>>(Cmat);
    // 3) descriptor matrix X (k-major)
    {
        dim3 grid(RR / 256, KP);
        buildx_kernel<<<grid, 256>>>(p0);
    }
    // 4) phi = X^T W + b
    {
        dim3 grid(RR / 128, DOUT / 64);
        gemmB_kernel<<<grid, 256>>>(conv_b);
    }
    // 5) row norms
    feat2_kernel<<<RR / 8, 256>>>();
    // 6) fused dist GEMM + top-3 + score
    {
        int smem = (448 * 68 + 16 * 64 + 64) * (int)sizeof(float);  // 126,208 B
        cudaFuncSetAttribute(gemmC_kernel, cudaFuncAttributeMaxDynamicSharedMemorySize, smem);
        gemmC_kernel<<<RR / 64, 256, smem>>>(Cmat, out);
    }
}

// round 2
// speedup vs baseline: 1.0637x; 1.0637x over previous
#include <cuda_runtime.h>
#include <math.h>

// ---------------- problem constants ----------------
#define BZ    8
#define HH    56
#define WW    56
#define HWP   3136        // 56*56
#define RR    25088       // BZ*HWP rows
#define C0N   256
#define C1N   512
#define C2N   1024
#define CIN   1794
#define KP    1808        // CIN padded to multiple of 16
#define DOUT  448
#define NC    3136        // number of centers

typedef unsigned long long ull;

// ---------------- scratch ----------------
__device__ float g_pool1[BZ * C1N * 28 * 28];
__device__ float g_pool2[BZ * C2N * 14 * 14];
__device__ float g_X[(size_t)KP * RR];               // X[k][r]  (k-major)
__device__ float g_Wp[KP * DOUT];                    // Wp[k][o]
__device__ float g_phiT[(size_t)DOUT * RR];          // phiT[o][r] (k-major for gemmC)
__device__ float g_feat2[RR];
__device__ float g_cent2[NC];

// ---------------- f32x2 helpers ----------------
__device__ __forceinline__ ull pk2(float x) {
    ull r;
    asm("mov.b64 %0, {%1, %1};" : "=l"(r) : "f"(x));
    return r;
}
__device__ __forceinline__ void fma2(ull& d, ull a, ull b) {
    asm("fma.rn.f32x2 %0, %1, %2, %0;" : "+l"(d) : "l"(a), "l"(b));
}
__device__ __forceinline__ float plo(ull p) { return __uint_as_float((unsigned)p); }
__device__ __forceinline__ float phi_(ull p) { return __uint_as_float((unsigned)(p >> 32)); }

// ---------------- misc helpers ----------------
__device__ __forceinline__ float bilin(const float* __restrict__ ch, int S, float u, float v) {
    int y0 = (int)floorf(u); float fy = u - (float)y0;
    int x0 = (int)floorf(v); float fx = v - (float)x0;
    int y0c = min(max(y0, 0), S - 1);
    int y1c = min(max(y0 + 1, 0), S - 1);
    int x0c = min(max(x0, 0), S - 1);
    int x1c = min(max(x0 + 1, 0), S - 1);
    float a = ch[y0c * S + x0c];
    float b = ch[y0c * S + x1c];
    float c = ch[y1c * S + x0c];
    float d = ch[y1c * S + x1c];
    return (1.f - fy) * ((1.f - fx) * a + fx * b) + fy * ((1.f - fx) * c + fx * d);
}

__device__ __forceinline__ void ins3(float v, float& a, float& b, float& c) {
    if (v < c) {
        if (v < b) {
            c = b;
            if (v < a) { b = a; a = v; } else { b = v; }
        } else {
            c = v;
        }
    }
}

// ---------------- stage 1: 3x3 avg pool for p1 / p2 ----------------
__global__ void pool_kernel(const float* __restrict__ in, int total, int S, int which) {
    int idx = blockIdx.x * 256 + threadIdx.x;
    if (idx >= total) return;
    int x = idx % S;
    int y = (idx / S) % S;
    int bc = idx / (S * S);
    const float* p = in + (size_t)bc * S * S;
    float s = 0.f;
    #pragma unroll
    for (int dy = -1; dy <= 1; dy++) {
        int yy = y + dy;
        if ((unsigned)yy >= (unsigned)S) continue;
        #pragma unroll
        for (int dx = -1; dx <= 1; dx++) {
            int xx = x + dx;
            if ((unsigned)xx >= (unsigned)S) continue;
            s += p[yy * S + xx];
        }
    }
    float* out = which ? g_pool2 : g_pool1;
    out[idx] = s * (1.f / 9.f);
}

// ---------------- stage 2: pack weights ----------------
__global__ void prepw_kernel(const float* __restrict__ w) {
    int idx = blockIdx.x * 256 + threadIdx.x;
    if (idx >= KP * DOUT) return;
    int k = idx / DOUT;
    int o = idx % DOUT;
    g_Wp[idx] = (k < CIN) ? w[o * CIN + k] : 0.f;
}

// ---------------- stage 3: center norms (8 lanes per center) ----------------
__global__ void cent2_kernel(const float* __restrict__ Cmat) {
    int gid = blockIdx.x * 256 + threadIdx.x;
    int n = gid >> 3;
    int part = gid & 7;
    if (n >= NC) return;
    float s = 0.f;
    for (int o = part; o < DOUT; o += 8) {
        float v = Cmat[(size_t)o * NC + n];
        s = fmaf(v, v, s);
    }
    s += __shfl_xor_sync(0xFFFFFFFFu, s, 1);
    s += __shfl_xor_sync(0xFFFFFFFFu, s, 2);
    s += __shfl_xor_sync(0xFFFFFFFFu, s, 4);
    if (part == 0) g_cent2[n] = s;
}

// ---------------- stage 4: build X (k-major) ----------------
__global__ void buildx_kernel(const float* __restrict__ p0) {
    int r = blockIdx.x * 256 + threadIdx.x;
    int k = blockIdx.y;
    int b = r / HWP;
    int pix = r - b * HWP;
    int h = pix / WW;
    int w = pix - h * WW;
    float val;
    if (k < C0N) {
        const float* p = p0 + (size_t)(b * C0N + k) * HWP;
        float s = 0.f;
        #pragma unroll
        for (int dy = -1; dy <= 1; dy++) {
            int y = h + dy;
            if ((unsigned)y >= (unsigned)HH) continue;
            #pragma unroll
            for (int dx = -1; dx <= 1; dx++) {
                int x = w + dx;
                if ((unsigned)x >= (unsigned)WW) continue;
                s += p[y * WW + x];
            }
        }
        val = s * (1.f / 9.f);
    } else if (k < C0N + C1N) {
        const float* ch = g_pool1 + (size_t)(b * C1N + (k - C0N)) * 784;
        val = bilin(ch, 28, h * 0.5f - 0.25f, w * 0.5f - 0.25f);
    } else if (k < C0N + C1N + C2N) {
        const float* ch = g_pool2 + (size_t)(b * C2N + (k - C0N - C1N)) * 196;
        val = bilin(ch, 14, h * 0.25f - 0.375f, w * 0.25f - 0.375f);
    } else if (k == 1792) {
        val = (float)h * (2.f / 55.f) - 1.f;
    } else if (k == 1793) {
        val = (float)w * (2.f / 55.f) - 1.f;
    } else {
        val = 0.f;
    }
    g_X[(size_t)k * RR + r] = val;
}

// ---------------- stage 5: GEMM B  phiT = (X^T * Wp + b)^T  ----------------
// Tile 256 rows x 64 outs, micro 8x8, f32x2, double-buffered smem.
__global__ void __launch_bounds__(256) gemmB_kernel(const float* __restrict__ bias) {
    __shared__ float As[2][16][256];
    __shared__ float Bs[2][16][64];
    int m0 = blockIdx.x * 256;
    int n0 = blockIdx.y * 64;
    int tid = threadIdx.x;
    int tm = tid & 31;       // 32 m-groups of 8 rows
    int tn = tid >> 5;       // warp id = n-group of 8 cols (broadcast B)

    // staging indices
    int ak[4], am4[4];
    #pragma unroll
    for (int it = 0; it < 4; it++) {
        int l = tid + it * 256;
        ak[it] = l >> 6;
        am4[it] = (l & 63) << 2;
    }
    int bk = tid >> 4;
    int bn4 = (tid & 15) << 2;

    ull acc[8][4];
    #pragma unroll
    for (int i = 0; i < 8; i++)
        #pragma unroll
        for (int j = 0; j < 4; j++) acc[i][j] = 0ull;

    float4 pa[4], pb;
    // prologue: chunk 0
    #pragma unroll
    for (int it = 0; it < 4; it++)
        pa[it] = *(const float4*)(g_X + (size_t)ak[it] * RR + m0 + am4[it]);
    pb = *(const float4*)(g_Wp + bk * DOUT + n0 + bn4);
    #pragma unroll
    for (int it = 0; it < 4; it++) *(float4*)&As[0][ak[it]][am4[it]] = pa[it];
    *(float4*)&Bs[0][bk][bn4] = pb;
    __syncthreads();

    const int NCHUNK = KP / 16;   // 113
    for (int c = 0; c < NCHUNK; c++) {
        int cur = c & 1;
        if (c + 1 < NCHUNK) {
            int kc = (c + 1) * 16;
            #pragma unroll
            for (int it = 0; it < 4; it++)
                pa[it] = *(const float4*)(g_X + (size_t)(kc + ak[it]) * RR + m0 + am4[it]);
            pb = *(const float4*)(g_Wp + (kc + bk) * DOUT + n0 + bn4);
        }
        #pragma unroll
        for (int k = 0; k < 16; k++) {
            float4 a0 = *(const float4*)&As[cur][k][tm * 8];
            float4 a1 = *(const float4*)&As[cur][k][tm * 8 + 4];
            ull ap[8];
            ap[0] = pk2(a0.x); ap[1] = pk2(a0.y); ap[2] = pk2(a0.z); ap[3] = pk2(a0.w);
            ap[4] = pk2(a1.x); ap[5] = pk2(a1.y); ap[6] = pk2(a1.z); ap[7] = pk2(a1.w);
            ulonglong2 b01 = *(const ulonglong2*)&Bs[cur][k][tn * 8];
            ulonglong2 b23 = *(const ulonglong2*)&Bs[cur][k][tn * 8 + 4];
            ull bp[4] = {b01.x, b01.y, b23.x, b23.y};
            #pragma unroll
            for (int i = 0; i < 8; i++)
                #pragma unroll
                for (int j = 0; j < 4; j++)
                    fma2(acc[i][j], ap[i], bp[j]);
        }
        if (c + 1 < NCHUNK) {
            int nxt = cur ^ 1;
            #pragma unroll
            for (int it = 0; it < 4; it++) *(float4*)&As[nxt][ak[it]][am4[it]] = pa[it];
            *(float4*)&Bs[nxt][bk][bn4] = pb;
        }
        __syncthreads();
    }

    // epilogue: bias + store phiT[o][r]
    #pragma unroll
    for (int j = 0; j < 4; j++) {
        int olo = n0 + tn * 8 + 2 * j;
        float blo = bias[olo];
        float bhi = bias[olo + 1];
        float vlo[8], vhi[8];
        #pragma unroll
        for (int i = 0; i < 8; i++) {
            vlo[i] = plo(acc[i][j]) + blo;
            vhi[i] = phi_(acc[i][j]) + bhi;
        }
        float4 s0 = {vlo[0], vlo[1], vlo[2], vlo[3]};
        float4 s1 = {vlo[4], vlo[5], vlo[6], vlo[7]};
        float4 s2 = {vhi[0], vhi[1], vhi[2], vhi[3]};
        float4 s3 = {vhi[4], vhi[5], vhi[6], vhi[7]};
        *(float4*)(g_phiT + (size_t)olo * RR + m0 + tm * 8) = s0;
        *(float4*)(g_phiT + (size_t)olo * RR + m0 + tm * 8 + 4) = s1;
        *(float4*)(g_phiT + (size_t)(olo + 1) * RR + m0 + tm * 8) = s2;
        *(float4*)(g_phiT + (size_t)(olo + 1) * RR + m0 + tm * 8 + 4) = s3;
    }
}

// ---------------- stage 6: row norms from phiT ----------------
__global__ void feat2_kernel() {
    int r = blockIdx.x * 256 + threadIdx.x;
    float s = 0.f;
    #pragma unroll 8
    for (int k = 0; k < DOUT; k++) {
        float v = g_phiT[(size_t)k * RR + r];
        s = fmaf(v, v, s);
    }
    g_feat2[r] = s;
}

// ---------------- stage 7: fused dist GEMM + top-3 + softmin score ----------------
// Tile 256 rows x 64 centers, 49 center tiles, micro 8x8, f32x2.
__global__ void __launch_bounds__(256) gemmC_kernel(const float* __restrict__ Cmat,
                                                    float* __restrict__ out) {
    __shared__ float As[2][16][256];
    __shared__ float Bs[2][16][64];
    __shared__ float c2S[64];
    int m0 = blockIdx.x * 256;
    int tid = threadIdx.x;
    int tm = tid & 31;
    int tn = tid >> 5;

    int ak[4], am4[4];
    #pragma unroll
    for (int it = 0; it < 4; it++) {
        int l = tid + it * 256;
        ak[it] = l >> 6;
        am4[it] = (l & 63) << 2;
    }
    int bk = tid >> 4;
    int bn4 = (tid & 15) << 2;

    const float BIG = 3.4e38f;
    float t0[8], t1[8], t2[8];
    #pragma unroll
    for (int i = 0; i < 8; i++) { t0[i] = BIG; t1[i] = BIG; t2[i] = BIG; }

    for (int n0 = 0; n0 < NC; n0 += 64) {
        __syncthreads();              // protect c2S / smem reuse
        if (tid < 64) c2S[tid] = g_cent2[n0 + tid];

        ull acc[8][4];
        #pragma unroll
        for (int i = 0; i < 8; i++)
            #pragma unroll
            for (int j = 0; j < 4; j++) acc[i][j] = 0ull;

        float4 pa[4], pb;
        // prologue chunk 0
        #pragma unroll
        for (int it = 0; it < 4; it++)
            pa[it] = *(const float4*)(g_phiT + (size_t)ak[it] * RR + m0 + am4[it]);
        pb = *(const float4*)(Cmat + (size_t)bk * NC + n0 + bn4);
        #pragma unroll
        for (int it = 0; it < 4; it++) *(float4*)&As[0][ak[it]][am4[it]] = pa[it];
        *(float4*)&Bs[0][bk][bn4] = pb;
        __syncthreads();

        const int NCHUNK = DOUT / 16;  // 28
        for (int c = 0; c < NCHUNK; c++) {
            int cur = c & 1;
            if (c + 1 < NCHUNK) {
                int kc = (c + 1) * 16;
                #pragma unroll
                for (int it = 0; it < 4; it++)
                    pa[it] = *(const float4*)(g_phiT + (size_t)(kc + ak[it]) * RR + m0 + am4[it]);
                pb = *(const float4*)(Cmat + (size_t)(kc + bk) * NC + n0 + bn4);
            }
            #pragma unroll
            for (int k = 0; k < 16; k++) {
                float4 a0 = *(const float4*)&As[cur][k][tm * 8];
                float4 a1 = *(const float4*)&As[cur][k][tm * 8 + 4];
                ull ap[8];
                ap[0] = pk2(a0.x); ap[1] = pk2(a0.y); ap[2] = pk2(a0.z); ap[3] = pk2(a0.w);
                ap[4] = pk2(a1.x); ap[5] = pk2(a1.y); ap[6] = pk2(a1.z); ap[7] = pk2(a1.w);
                ulonglong2 b01 = *(const ulonglong2*)&Bs[cur][k][tn * 8];
                ulonglong2 b23 = *(const ulonglong2*)&Bs[cur][k][tn * 8 + 4];
                ull bp[4] = {b01.x, b01.y, b23.x, b23.y};
                #pragma unroll
                for (int i = 0; i < 8; i++)
                    #pragma unroll
                    for (int j = 0; j < 4; j++)
                        fma2(acc[i][j], ap[i], bp[j]);
            }
            if (c + 1 < NCHUNK) {
                int nxt = cur ^ 1;
                #pragma unroll
                for (int it = 0; it < 4; it++) *(float4*)&As[nxt][ak[it]][am4[it]] = pa[it];
                *(float4*)&Bs[nxt][bk][bn4] = pb;
            }
            __syncthreads();
        }

        // per-tile top-3 update: key = |c|^2 - 2*dot
        #pragma unroll
        for (int j = 0; j < 4; j++) {
            float c2lo = c2S[tn * 8 + 2 * j];
            float c2hi = c2S[tn * 8 + 2 * j + 1];
            #pragma unroll
            for (int i = 0; i < 8; i++) {
                float klo = c2lo - 2.f * plo(acc[i][j]);
                float khi = c2hi - 2.f * phi_(acc[i][j]);
                ins3(klo, t0[i], t1[i], t2[i]);
                ins3(khi, t0[i], t1[i], t2[i]);
            }
        }
    }

    // merge across 8 n-groups: cand[row][24], reuse As
    float* cand = &As[0][0][0];       // 256*24 floats = 6144 <= 8192
    __syncthreads();
    #pragma unroll
    for (int i = 0; i < 8; i++) {
        int m = tm * 8 + i;
        cand[m * 24 + tn * 3 + 0] = t0[i];
        cand[m * 24 + tn * 3 + 1] = t1[i];
        cand[m * 24 + tn * 3 + 2] = t2[i];
    }
    __syncthreads();

    {
        int m = tid;
        float k0 = BIG, k1 = BIG, k2 = BIG;
        #pragma unroll
        for (int j = 0; j < 24; j++) {
            float v = cand[m * 24 + j];
            ins3(v, k0, k1, k2);
        }
        float f2 = g_feat2[m0 + m];
        float d0 = sqrtf(f2 + k0);
        float d1 = sqrtf(f2 + k1);
        float d2 = sqrtf(f2 + k2);
        float s = 1.f / (1.f + expf(d0 - d1) + expf(d0 - d2));
        out[m0 + m] = d0 * s;
    }
}

// ---------------- launch ----------------
extern "C" void kernel_launch(void* const* d_in, const int* in_sizes, int n_in,
                              void* d_out, int out_size) {
    (void)in_sizes; (void)n_in; (void)out_size;
    const float* p0     = (const float*)d_in[0];
    const float* p1     = (const float*)d_in[1];
    const float* p2     = (const float*)d_in[2];
    const float* conv_w = (const float*)d_in[3];
    const float* conv_b = (const float*)d_in[4];
    const float* Cmat   = (const float*)d_in[5];
    float* out = (float*)d_out;

    {
        int t1 = BZ * C1N * 28 * 28;
        pool_kernel<<<(t1 + 255) / 256, 256>>>(p1, t1, 28, 0);
        int t2 = BZ * C2N * 14 * 14;
        pool_kernel<<<(t2 + 255) / 256, 256>>>(p2, t2, 14, 1);
    }
    prepw_kernel<<<(KP * DOUT + 255) / 256, 256>>>(conv_w);
    cent2_kernel<<<(NC * 8 + 255) / 256, 256>>>(Cmat);
    {
        dim3 grid(RR / 256, KP);
        buildx_kernel<<<grid, 256>>>(p0);
    }
    {
        dim3 grid(RR / 256, DOUT / 64);
        gemmB_kernel<<<grid, 256>>>(conv_b);
    }
    feat2_kernel<<<RR / 256, 256>>>();
    gemmC_kernel<<<RR / 256, 256>>>(Cmat, out);
}

// round 4
// speedup vs baseline: 2.4750x; 2.3269x over previous
#include <cuda_runtime.h>
#include <cuda_bf16.h>
#include <mma.h>
#include <math.h>
#include <stdint.h>

// ---------------- problem constants ----------------
#define BZ    8
#define HH    56
#define WW    56
#define HWP   3136
#define RR    25088       // BZ*HWP rows
#define C0N   256
#define C1N   512
#define C2N   1024
#define CIN   1794
#define DOUT  448
#define NC    3136

#define KBP   1856        // gemmB K padded (29*64)
#define XSTR  (2*KBP)     // 3712 (hi plane + lo plane)
#define KCP   448         // gemmC K (7*64)
#define PSTR  (2*KCP)     // 896

#define SEG_B (KBP/64)    // 29 chunks per plane-product
#define NCH_B (3*SEG_B)   // 87
#define SEG_C (KCP/64)    // 7
#define NCH_C (3*SEG_C)   // 21
#define NTILE 224
#define NT_C  (NC/NTILE)  // 14

#if defined(__CUDA_ARCH_FEAT_SM103_ALL)
#define USE_TCGEN05 1
#else
#define USE_TCGEN05 0
#endif

// ---------------- scratch ----------------
__device__ float g_pool1[BZ * C1N * 28 * 28];
__device__ float g_pool2[BZ * C2N * 14 * 14];
__device__ float g_feat2[RR];
__device__ float g_cent2[NC];
__device__ __align__(16) unsigned short gXt[(size_t)RR * XSTR];   // 186 MB
__device__ __align__(16) unsigned short gWt[(size_t)DOUT * XSTR]; // 3.3 MB
__device__ __align__(16) unsigned short gPhiT[(size_t)RR * PSTR]; // 45 MB
__device__ __align__(16) unsigned short gCt[(size_t)NC * PSTR];   // 5.6 MB

// ---------------- PTX helpers ----------------
__device__ __forceinline__ uint32_t smem_u32(const void* p) {
    uint32_t a;
    asm("{ .reg .u64 t; cvta.to.shared.u64 t, %1; cvt.u32.u64 %0, t; }" : "=r"(a) : "l"(p));
    return a;
}

#if USE_TCGEN05
__device__ __forceinline__ uint32_t elect_one() {
    uint32_t pred;
    asm volatile("{ .reg .pred p; elect.sync _|p, 0xFFFFFFFF; selp.b32 %0, 1, 0, p; }" : "=r"(pred));
    return pred;
}
#define TC_ALLOC(addr, n) \
    asm volatile("tcgen05.alloc.cta_group::1.sync.aligned.shared::cta.b32 [%0], %1;" :: "r"(addr), "r"(n) : "memory")
#define TC_DEALLOC(t, n) \
    asm volatile("tcgen05.dealloc.cta_group::1.sync.aligned.b32 %0, %1;" :: "r"(t), "r"(n))
#define TC_RELINQ() \
    asm volatile("tcgen05.relinquish_alloc_permit.cta_group::1.sync.aligned;")
#define TC_COMMIT(mb) \
    asm volatile("tcgen05.commit.cta_group::1.mbarrier::arrive::one.shared::cluster.b64 [%0];" :: "r"(mb) : "memory")
#define TC_FENCE_BEFORE() asm volatile("tcgen05.fence::before_thread_sync;" ::: "memory")
#define TC_FENCE_AFTER()  asm volatile("tcgen05.fence::after_thread_sync;" ::: "memory")
#define TC_WAIT_LD()      asm volatile("tcgen05.wait::ld.sync.aligned;" ::: "memory")
#define FENCE_PROXY()     asm volatile("fence.proxy.async.shared::cta;" ::: "memory")
#define MBAR_INIT(mb, cnt) \
    asm volatile("mbarrier.init.shared.b64 [%0], %1;" :: "r"(mb), "r"(cnt) : "memory")

#define MBAR_WAIT(mb, par) do {                                                   \
    uint32_t _m = (mb), _p = (par), _d;                                           \
    asm volatile("{ .reg .pred p; mbarrier.try_wait.parity.acquire.cta.shared::cta.b64 p, [%1], %2; selp.b32 %0,1,0,p; }" \
        : "=r"(_d) : "r"(_m), "r"(_p) : "memory");                                \
    if (!_d) {                                                                    \
        asm volatile("{ .reg .pred P1; WL_%=: mbarrier.try_wait.parity.acquire.cta.shared::cta.b64 P1, [%0], %1, 0x989680; @P1 bra.uni WD_%=; bra.uni WL_%=; WD_%=: }" \
            :: "r"(_m), "r"(_p) : "memory");                                      \
    }                                                                             \
} while (0)

#define LDTM_X32(r, t) \
    asm volatile("tcgen05.ld.sync.aligned.32x32b.x32.b32 " \
        "{%0,%1,%2,%3,%4,%5,%6,%7,%8,%9,%10,%11,%12,%13,%14,%15," \
        "%16,%17,%18,%19,%20,%21,%22,%23,%24,%25,%26,%27,%28,%29,%30,%31}, [%32];" \
        : "=r"((r)[0]),"=r"((r)[1]),"=r"((r)[2]),"=r"((r)[3]),"=r"((r)[4]),"=r"((r)[5]),"=r"((r)[6]),"=r"((r)[7]), \
          "=r"((r)[8]),"=r"((r)[9]),"=r"((r)[10]),"=r"((r)[11]),"=r"((r)[12]),"=r"((r)[13]),"=r"((r)[14]),"=r"((r)[15]), \
          "=r"((r)[16]),"=r"((r)[17]),"=r"((r)[18]),"=r"((r)[19]),"=r"((r)[20]),"=r"((r)[21]),"=r"((r)[22]),"=r"((r)[23]), \
          "=r"((r)[24]),"=r"((r)[25]),"=r"((r)[26]),"=r"((r)[27]),"=r"((r)[28]),"=r"((r)[29]),"=r"((r)[30]),"=r"((r)[31]) \
        : "r"(t))

// SW128 smem descriptor (LBO=1, SBO=64, version=1, layout=SW128)
__device__ __forceinline__ uint64_t mk_desc(uint32_t addr) {
    const uint64_t BASE = (uint64_t(2) << 61) | (uint64_t(1) << 46) |
                          (uint64_t(64) << 32) | (uint64_t(1) << 16);
    return BASE | ((uint64_t)(addr >> 4) & 0x3FFF);
}

// idesc: F32 acc, BF16 a/b, M=128, N=224
#define IDESC_224 ((1u<<4)|(1u<<7)|(1u<<10)|(28u<<17)|(8u<<24))

__device__ __forceinline__ void mma_ss(uint32_t d, uint64_t ad, uint64_t bd,
                                       uint32_t idesc, uint32_t acc) {
    asm volatile(
        "{ .reg .pred p; setp.ne.u32 p, %4, 0;\n\t"
        "tcgen05.mma.cta_group::1.kind::f16 [%0], %1, %2, %3, {%5,%5,%5,%5}, p; }"
        :: "r"(d), "l"(ad), "l"(bd), "r"(idesc), "r"(acc), "r"(0u) : "memory");
}
#endif // USE_TCGEN05

// ---------------- bf16 split helpers ----------------
__device__ __forceinline__ unsigned short f2bf(float x) {
    __nv_bfloat16 h = __float2bfloat16(x);
    unsigned short u; memcpy(&u, &h, 2); return u;
}
__device__ __forceinline__ float bf2f(unsigned short u) {
    __nv_bfloat16 h; memcpy(&h, &u, 2); return __bfloat162float(h);
}

__device__ __forceinline__ void ins3(float v, float& a, float& b, float& c) {
    if (v < c) {
        if (v < b) { c = b; if (v < a) { b = a; a = v; } else b = v; }
        else c = v;
    }
}

__device__ __forceinline__ float bilin(const float* __restrict__ ch, int S, float u, float v) {
    int y0 = (int)floorf(u); float fy = u - (float)y0;
    int x0 = (int)floorf(v); float fx = v - (float)x0;
    int y0c = min(max(y0, 0), S - 1);
    int y1c = min(max(y0 + 1, 0), S - 1);
    int x0c = min(max(x0, 0), S - 1);
    int x1c = min(max(x0 + 1, 0), S - 1);
    float a = ch[y0c * S + x0c], b = ch[y0c * S + x1c];
    float c = ch[y1c * S + x0c], d = ch[y1c * S + x1c];
    return (1.f - fy) * ((1.f - fx) * a + fx * b) + fy * ((1.f - fx) * c + fx * d);
}

#if USE_TCGEN05
// stage NROWS x 128B into SW128-swizzled smem tile
template<int NROWS>
__device__ __forceinline__ void stage(const unsigned short* __restrict__ src,
                                      size_t rstride, char* dst, int tid) {
    #pragma unroll
    for (int s = 0; s < NROWS * 8 / 256; s++) {
        int l = tid + s * 256;
        int row = l >> 3, c = l & 7;
        uint4 v = *(const uint4*)(src + (size_t)row * rstride + c * 8);
        unsigned off = row * 128 + c * 16;
        off ^= (off >> 3) & 0x70;
        *(uint4*)(dst + off) = v;
    }
}
#else
// fallback: stage NROWS x 64 bf16 into padded stride-72 smem
template<int NROWS>
__device__ __forceinline__ void fstage(const unsigned short* __restrict__ src,
                                       size_t rstride, unsigned short* dst, int tid) {
    #pragma unroll
    for (int s = 0; s < NROWS * 8 / 256; s++) {
        int l = tid + s * 256;
        int row = l >> 3, c = l & 7;
        uint4 v = *(const uint4*)(src + (size_t)row * rstride + c * 8);
        *(uint4*)(dst + row * 72 + c * 8) = v;
    }
}
#endif

// fallback smem layout (bytes)
#define FB_A0  0
#define FB_A1  18432
#define FB_B0  36864
#define FB_B1  46080
#define FB_CS  55296            // 128*72*4 = 36864
#define FB_AUX 92160            // bias / cent2 staging (64 floats)

// ---------------- stage 1: pools for p1/p2 ----------------
__global__ void pool_kernel(const float* __restrict__ in, int total, int S, int which) {
    int idx = blockIdx.x * 256 + threadIdx.x;
    if (idx >= total) return;
    int x = idx % S, y = (idx / S) % S, bc = idx / (S * S);
    const float* p = in + (size_t)bc * S * S;
    float s = 0.f;
    #pragma unroll
    for (int dy = -1; dy <= 1; dy++) {
        int yy = y + dy; if ((unsigned)yy >= (unsigned)S) continue;
        #pragma unroll
        for (int dx = -1; dx <= 1; dx++) {
            int xx = x + dx; if ((unsigned)xx >= (unsigned)S) continue;
            s += p[yy * S + xx];
        }
    }
    (which ? g_pool2 : g_pool1)[idx] = s * (1.f / 9.f);
}

// ---------------- stage 2: weight/center packing ----------------
__global__ void prepW_kernel(const float* __restrict__ w) {
    int idx = blockIdx.x * 256 + threadIdx.x;
    if (idx >= DOUT * KBP) return;
    int o = idx / KBP, k = idx - o * KBP;
    float v = (k < CIN) ? w[o * CIN + k] : 0.f;
    unsigned short h = f2bf(v);
    gWt[(size_t)o * XSTR + k] = h;
    gWt[(size_t)o * XSTR + KBP + k] = f2bf(v - bf2f(h));
}

__global__ void prepC_kernel(const float* __restrict__ Cmat) {
    int idx = blockIdx.x * 256 + threadIdx.x;
    if (idx >= NC * KCP) return;
    int k = idx / NC, n = idx - k * NC;
    float v = Cmat[(size_t)k * NC + n];
    unsigned short h = f2bf(v);
    gCt[(size_t)n * PSTR + k] = h;
    gCt[(size_t)n * PSTR + KCP + k] = f2bf(v - bf2f(h));
}

__global__ void cent2_kernel(const float* __restrict__ Cmat) {
    int gid = blockIdx.x * 256 + threadIdx.x;
    int n = gid >> 3, part = gid & 7;
    if (n >= NC) return;
    float s = 0.f;
    for (int o = part; o < DOUT; o += 8) {
        float v = Cmat[(size_t)o * NC + n];
        s = fmaf(v, v, s);
    }
    s += __shfl_xor_sync(0xFFFFFFFFu, s, 1);
    s += __shfl_xor_sync(0xFFFFFFFFu, s, 2);
    s += __shfl_xor_sync(0xFFFFFFFFu, s, 4);
    if (part == 0) g_cent2[n] = s;
}

// ---------------- stage 3: build X row-major bf16 hi/lo via smem transpose ----------------
__global__ void buildx_kernel(const float* __restrict__ p0) {
    __shared__ float s[64][65];
    int rt0 = blockIdx.x * 64;
    int kt0 = blockIdx.y * 64;
    int tid = threadIdx.x;
    int rr = tid & 63;
    int r = rt0 + rr;
    int b = r / HWP;
    int pix = r - b * HWP;
    int h = pix / WW, w = pix - h * WW;

    #pragma unroll 1
    for (int i = 0; i < 16; i++) {
        int kk = (tid >> 6) * 16 + i;
        int k = kt0 + kk;
        float val;
        if (k < C0N) {
            const float* p = p0 + (size_t)(b * C0N + k) * HWP;
            float acc = 0.f;
            #pragma unroll
            for (int dy = -1; dy <= 1; dy++) {
                int y = h + dy; if ((unsigned)y >= (unsigned)HH) continue;
                #pragma unroll
                for (int dx = -1; dx <= 1; dx++) {
                    int x = w + dx; if ((unsigned)x >= (unsigned)WW) continue;
                    acc += p[y * WW + x];
                }
            }
            val = acc * (1.f / 9.f);
        } else if (k < C0N + C1N) {
            const float* ch = g_pool1 + (size_t)(b * C1N + (k - C0N)) * 784;
            val = bilin(ch, 28, h * 0.5f - 0.25f, w * 0.5f - 0.25f);
        } else if (k < C0N + C1N + C2N) {
            const float* ch = g_pool2 + (size_t)(b * C2N + (k - C0N - C1N)) * 196;
            val = bilin(ch, 14, h * 0.25f - 0.375f, w * 0.25f - 0.375f);
        } else if (k == 1792) {
            val = (float)h * (2.f / 55.f) - 1.f;
        } else if (k == 1793) {
            val = (float)w * (2.f / 55.f) - 1.f;
        } else {
            val = 0.f;
        }
        s[kk][rr] = val;
    }
    __syncthreads();

    #pragma unroll
    for (int it = 0; it < 2; it++) {
        int sg = tid + it * 256;
        int row = sg >> 3, c8 = (sg & 7) * 8;
        unsigned hw[4], lw[4];
        #pragma unroll
        for (int j = 0; j < 8; j += 2) {
            float v0 = s[c8 + j][row], v1 = s[c8 + j + 1][row];
            unsigned short h0 = f2bf(v0), h1 = f2bf(v1);
            unsigned short l0 = f2bf(v0 - bf2f(h0)), l1 = f2bf(v1 - bf2f(h1));
            hw[j >> 1] = (unsigned)h0 | ((unsigned)h1 << 16);
            lw[j >> 1] = (unsigned)l0 | ((unsigned)l1 << 16);
        }
        size_t base = (size_t)(rt0 + row) * XSTR + kt0 + c8;
        *(uint4*)(gXt + base)       = make_uint4(hw[0], hw[1], hw[2], hw[3]);
        *(uint4*)(gXt + base + KBP) = make_uint4(lw[0], lw[1], lw[2], lw[3]);
    }
}

// ---------------- stage 4: GEMM-B: phi = X * W^T + b  (M=128/block, N=448) ----------------
#define B_A0 1024
#define B_A1 (1024 + 16384)
#define B_B0 (1024 + 32768)
#define B_B1 (1024 + 32768 + 57344)
#define B_SMEM (1024 + 32768 + 2 * 57344)

__global__ void __launch_bounds__(256)
gemmB_kernel(const float* __restrict__ bias) {
    extern __shared__ char smc[];
    int tid = threadIdx.x, wid = tid >> 5, lane = tid & 31;
    int r0 = blockIdx.x * 128;

#if USE_TCGEN05
    uint32_t smb = smem_u32(smc);
    if (wid == 0) { TC_ALLOC(smb, 512); TC_RELINQ(); }
    if (tid == 0) { MBAR_INIT(smb + 8, 1); MBAR_INIT(smb + 16, 1); }
    __syncthreads();
    uint32_t tmem;
    asm volatile("ld.shared.b32 %0, [%1];" : "=r"(tmem) : "r"(smb));

    const unsigned AOFF[2] = {B_A0, B_A1};
    const unsigned BOFF[2] = {B_B0, B_B1};

    #pragma unroll 1
    for (int g = 0; g < NCH_B; g++) {
        int buf = g & 1;
        if (g >= 2) MBAR_WAIT(smb + 8 + buf * 8, ((g - 2) >> 1) & 1);
        int seg = (g < SEG_B) ? 0 : (g < 2 * SEG_B ? 1 : 2);
        int kb = (g - seg * SEG_B) * 64;
        int pa = (seg == 2) ? KBP : 0;
        int pb = (seg == 1) ? KBP : 0;
        stage<128>(gXt + (size_t)r0 * XSTR + pa + kb, XSTR, smc + AOFF[buf], tid);
        stage<448>(gWt + pb + kb, XSTR, smc + BOFF[buf], tid);
        FENCE_PROXY();
        __syncthreads();
        if (wid == 0 && elect_one()) {
            uint64_t ad = mk_desc(smb + AOFF[buf]);
            uint64_t bd = mk_desc(smb + BOFF[buf]);
            #pragma unroll
            for (int ks = 0; ks < 4; ks++) {
                uint32_t acc = (g > 0) | (ks > 0);
                mma_ss(tmem,       ad + ks * 2, bd + ks * 2,        IDESC_224, acc);
                mma_ss(tmem + 224, ad + ks * 2, bd + ks * 2 + 1792, IDESC_224, acc);
            }
            TC_COMMIT(smb + 8 + buf * 8);
        }
    }
    {
        int g = NCH_B - 1;
        MBAR_WAIT(smb + 8 + (g & 1) * 8, (g >> 1) & 1);
    }
    TC_FENCE_AFTER();

    if (wid < 4) {
        int row = wid * 32 + lane;
        size_t r = (size_t)r0 + row;
        float ss = 0.f;
        #pragma unroll 1
        for (int cb = 0; cb < 14; cb++) {
            uint32_t rg[32];
            LDTM_X32(rg, tmem + cb * 32);
            TC_WAIT_LD();
            unsigned hw[16], lw[16];
            #pragma unroll
            for (int j = 0; j < 32; j += 2) {
                float v0 = __uint_as_float(rg[j])     + bias[cb * 32 + j];
                float v1 = __uint_as_float(rg[j + 1]) + bias[cb * 32 + j + 1];
                ss = fmaf(v0, v0, ss);
                ss = fmaf(v1, v1, ss);
                unsigned short h0 = f2bf(v0), h1 = f2bf(v1);
                unsigned short l0 = f2bf(v0 - bf2f(h0)), l1 = f2bf(v1 - bf2f(h1));
                hw[j >> 1] = (unsigned)h0 | ((unsigned)h1 << 16);
                lw[j >> 1] = (unsigned)l0 | ((unsigned)l1 << 16);
            }
            uint4* dh = (uint4*)(gPhiT + r * PSTR + cb * 32);
            uint4* dl = (uint4*)(gPhiT + r * PSTR + KCP + cb * 32);
            #pragma unroll
            for (int q = 0; q < 4; q++) {
                dh[q] = make_uint4(hw[q * 4], hw[q * 4 + 1], hw[q * 4 + 2], hw[q * 4 + 3]);
                dl[q] = make_uint4(lw[q * 4], lw[q * 4 + 1], lw[q * 4 + 2], lw[q * 4 + 3]);
            }
        }
        g_feat2[r] = ss;
    }
    __syncthreads();
    if (wid == 0) TC_DEALLOC(tmem, 512);

#else  // ------------- wmma fallback -------------
    using namespace nvcuda;
    unsigned short* smu = (unsigned short*)smc;
    float* Cs = (float*)(smc + FB_CS);
    float* biasS = (float*)(smc + FB_AUX);
    unsigned short* Abuf[2] = {(unsigned short*)(smc + FB_A0), (unsigned short*)(smc + FB_A1)};
    unsigned short* Bbuf[2] = {(unsigned short*)(smc + FB_B0), (unsigned short*)(smc + FB_B1)};
    (void)smu;

    int wm = wid & 3, wn = wid >> 2;
    float ss = 0.f;

    #pragma unroll 1
    for (int nt = 0; nt < DOUT / 64; nt++) {
        int n0 = nt * 64;
        if (tid < 64) biasS[tid] = bias[n0 + tid];

        wmma::fragment<wmma::accumulator, 16, 16, 16, float> cf[2][2];
        #pragma unroll
        for (int i = 0; i < 2; i++)
            #pragma unroll
            for (int j = 0; j < 2; j++) wmma::fill_fragment(cf[i][j], 0.f);

        // prologue: chunk 0
        fstage<128>(gXt + (size_t)r0 * XSTR, XSTR, Abuf[0], tid);
        fstage<64>(gWt + (size_t)n0 * XSTR, XSTR, Bbuf[0], tid);
        __syncthreads();

        #pragma unroll 1
        for (int c = 0; c < NCH_B; c++) {
            if (c + 1 < NCH_B) {
                int c1 = c + 1;
                int seg = c1 / SEG_B;
                int kb = (c1 - seg * SEG_B) * 64;
                int pa = (seg == 2) ? KBP : 0;
                int pb = (seg == 1) ? KBP : 0;
                fstage<128>(gXt + (size_t)r0 * XSTR + pa + kb, XSTR, Abuf[c1 & 1], tid);
                fstage<64>(gWt + (size_t)n0 * XSTR + pb + kb, XSTR, Bbuf[c1 & 1], tid);
            }
            const __nv_bfloat16* Ap = (const __nv_bfloat16*)Abuf[c & 1];
            const __nv_bfloat16* Bp = (const __nv_bfloat16*)Bbuf[c & 1];
            #pragma unroll
            for (int ks = 0; ks < 4; ks++) {
                wmma::fragment<wmma::matrix_b, 16, 16, 16, __nv_bfloat16, wmma::col_major> bf[2];
                wmma::load_matrix_sync(bf[0], Bp + (wn * 32) * 72 + ks * 16, 72);
                wmma::load_matrix_sync(bf[1], Bp + (wn * 32 + 16) * 72 + ks * 16, 72);
                #pragma unroll
                for (int i = 0; i < 2; i++) {
                    wmma::fragment<wmma::matrix_a, 16, 16, 16, __nv_bfloat16, wmma::row_major> af;
                    wmma::load_matrix_sync(af, Ap + (wm * 32 + i * 16) * 72 + ks * 16, 72);
                    wmma::mma_sync(cf[i][0], af, bf[0], cf[i][0]);
                    wmma::mma_sync(cf[i][1], af, bf[1], cf[i][1]);
                }
            }
            __syncthreads();
        }

        // epilogue through smem C tile
        #pragma unroll
        for (int i = 0; i < 2; i++)
            #pragma unroll
            for (int j = 0; j < 2; j++)
                wmma::store_matrix_sync(Cs + (wm * 32 + i * 16) * 72 + wn * 32 + j * 16,
                                        cf[i][j], 72, wmma::mem_row_major);
        __syncthreads();

        if (tid < 128) {
            const float* crow = Cs + tid * 72;
            size_t r = (size_t)r0 + tid;
            unsigned hw[16], lw[16];
            #pragma unroll
            for (int j = 0; j < 64; j += 2) {
                float v0 = crow[j] + biasS[j];
                float v1 = crow[j + 1] + biasS[j + 1];
                ss = fmaf(v0, v0, ss);
                ss = fmaf(v1, v1, ss);
                unsigned short h0 = f2bf(v0), h1 = f2bf(v1);
                unsigned short l0 = f2bf(v0 - bf2f(h0)), l1 = f2bf(v1 - bf2f(h1));
                hw[j >> 1] = (unsigned)h0 | ((unsigned)h1 << 16);
                lw[j >> 1] = (unsigned)l0 | ((unsigned)l1 << 16);
            }
            uint4* dh = (uint4*)(gPhiT + r * PSTR + n0);
            uint4* dl = (uint4*)(gPhiT + r * PSTR + KCP + n0);
            #pragma unroll
            for (int q = 0; q < 8; q++) {
                dh[q] = make_uint4(hw[q * 4 % 32], hw[q * 4 % 32 + 1], hw[q * 4 % 32 + 2], hw[q * 4 % 32 + 3]);
            }
            // note: hw/lw hold 32 packed words = 64 bf16 → 4 uint4 each
            uint4* dh2 = (uint4*)(gPhiT + r * PSTR + n0);
            uint4* dl2 = (uint4*)(gPhiT + r * PSTR + KCP + n0);
            #pragma unroll
            for (int q = 0; q < 4; q++) {
                dh2[q] = make_uint4(hw[q * 4], hw[q * 4 + 1], hw[q * 4 + 2], hw[q * 4 + 3]);
                dl2[q] = make_uint4(lw[q * 4], lw[q * 4 + 1], lw[q * 4 + 2], lw[q * 4 + 3]);
            }
        }
        __syncthreads();
    }
    if (tid < 128) g_feat2[r0 + tid] = ss;
#endif
}

// ---------------- stage 5: GEMM-C + fused top-3 + softmin ----------------
#define C_A0 1024
#define C_A1 (1024 + 16384)
#define C_B0 (1024 + 32768)
#define C_B1 (1024 + 32768 + 28672)
#define C_SMEM 98304

__global__ void __launch_bounds__(256)
gemmC_kernel(float* __restrict__ out) {
    extern __shared__ char smc[];
    int tid = threadIdx.x, wid = tid >> 5, lane = tid & 31;
    int r0 = blockIdx.x * 128;
    const float BIG = 3.4e38f;

#if USE_TCGEN05
    uint32_t smb = smem_u32(smc);
    if (wid == 0) { TC_ALLOC(smb, 512); TC_RELINQ(); }
    if (tid == 0) { MBAR_INIT(smb + 8, 1); MBAR_INIT(smb + 16, 1); }
    __syncthreads();
    uint32_t tmem;
    asm volatile("ld.shared.b32 %0, [%1];" : "=r"(tmem) : "r"(smb));

    const unsigned AOFF[2] = {C_A0, C_A1};
    const unsigned BOFF[2] = {C_B0, C_B1};

    float t0 = BIG, t1 = BIG, t2 = BIG;
    int row = (wid & 3) * 32 + lane;

    #pragma unroll 1
    for (int nt = 0; nt < NT_C; nt++) {
        int n0 = nt * NTILE;
        #pragma unroll 1
        for (int c = 0; c < NCH_C; c++) {
            int g = nt * NCH_C + c;
            int buf = g & 1;
            if (g >= 2) MBAR_WAIT(smb + 8 + buf * 8, ((g - 2) >> 1) & 1);
            int seg = (c < SEG_C) ? 0 : (c < 2 * SEG_C ? 1 : 2);
            int kb = (c - seg * SEG_C) * 64;
            int pa = (seg == 2) ? KCP : 0;
            int pb = (seg == 1) ? KCP : 0;
            stage<128>(gPhiT + (size_t)r0 * PSTR + pa + kb, PSTR, smc + AOFF[buf], tid);
            stage<224>(gCt + (size_t)n0 * PSTR + pb + kb, PSTR, smc + BOFF[buf], tid);
            FENCE_PROXY();
            __syncthreads();
            if (wid == 0 && elect_one()) {
                uint64_t ad = mk_desc(smb + AOFF[buf]);
                uint64_t bd = mk_desc(smb + BOFF[buf]);
                #pragma unroll
                for (int ks = 0; ks < 4; ks++) {
                    uint32_t acc = (c > 0) | (ks > 0);
                    mma_ss(tmem, ad + ks * 2, bd + ks * 2, IDESC_224, acc);
                }
                TC_COMMIT(smb + 8 + buf * 8);
            }
        }
        {
            int ge = nt * NCH_C + NCH_C - 1;
            MBAR_WAIT(smb + 8 + (ge & 1) * 8, (ge >> 1) & 1);
        }
        TC_FENCE_AFTER();
        if (wid < 4) {
            #pragma unroll 1
            for (int cb = 0; cb < 7; cb++) {
                uint32_t rg[32];
                LDTM_X32(rg, tmem + cb * 32);
                TC_WAIT_LD();
                #pragma unroll
                for (int j = 0; j < 32; j++) {
                    int n = n0 + cb * 32 + j;
                    float key = g_cent2[n] - 2.f * __uint_as_float(rg[j]);
                    ins3(key, t0, t1, t2);
                }
            }
        }
        TC_FENCE_BEFORE();
        __syncthreads();
    }

    if (wid < 4) {
        size_t r = (size_t)r0 + row;
        float f2 = g_feat2[r];
        float d0 = sqrtf(fmaxf(f2 + t0, 0.f));
        float d1 = sqrtf(fmaxf(f2 + t1, 0.f));
        float d2 = sqrtf(fmaxf(f2 + t2, 0.f));
        float s = 1.f / (1.f + expf(d0 - d1) + expf(d0 - d2));
        out[r] = d0 * s;
    }
    __syncthreads();
    if (wid == 0) TC_DEALLOC(tmem, 512);

#else  // ------------- wmma fallback -------------
    using namespace nvcuda;
    float* Cs = (float*)(smc + FB_CS);
    float* c2S = (float*)(smc + FB_AUX);
    unsigned short* Abuf[2] = {(unsigned short*)(smc + FB_A0), (unsigned short*)(smc + FB_A1)};
    unsigned short* Bbuf[2] = {(unsigned short*)(smc + FB_B0), (unsigned short*)(smc + FB_B1)};

    int wm = wid & 3, wn = wid >> 2;
    float t0 = BIG, t1 = BIG, t2 = BIG;
    const int NCHF = 3 * SEG_C;  // 21

    #pragma unroll 1
    for (int nt = 0; nt < NC / 64; nt++) {
        int n0 = nt * 64;
        if (tid < 64) c2S[tid] = g_cent2[n0 + tid];

        wmma::fragment<wmma::accumulator, 16, 16, 16, float> cf[2][2];
        #pragma unroll
        for (int i = 0; i < 2; i++)
            #pragma unroll
            for (int j = 0; j < 2; j++) wmma::fill_fragment(cf[i][j], 0.f);

        fstage<128>(gPhiT + (size_t)r0 * PSTR, PSTR, Abuf[0], tid);
        fstage<64>(gCt + (size_t)n0 * PSTR, PSTR, Bbuf[0], tid);
        __syncthreads();

        #pragma unroll 1
        for (int c = 0; c < NCHF; c++) {
            if (c + 1 < NCHF) {
                int c1 = c + 1;
                int seg = c1 / SEG_C;
                int kb = (c1 - seg * SEG_C) * 64;
                int pa = (seg == 2) ? KCP : 0;
                int pb = (seg == 1) ? KCP : 0;
                fstage<128>(gPhiT + (size_t)r0 * PSTR + pa + kb, PSTR, Abuf[c1 & 1], tid);
                fstage<64>(gCt + (size_t)n0 * PSTR + pb + kb, PSTR, Bbuf[c1 & 1], tid);
            }
            const __nv_bfloat16* Ap = (const __nv_bfloat16*)Abuf[c & 1];
            const __nv_bfloat16* Bp = (const __nv_bfloat16*)Bbuf[c & 1];
            #pragma unroll
            for (int ks = 0; ks < 4; ks++) {
                wmma::fragment<wmma::matrix_b, 16, 16, 16, __nv_bfloat16, wmma::col_major> bf[2];
                wmma::load_matrix_sync(bf[0], Bp + (wn * 32) * 72 + ks * 16, 72);
                wmma::load_matrix_sync(bf[1], Bp + (wn * 32 + 16) * 72 + ks * 16, 72);
                #pragma unroll
                for (int i = 0; i < 2; i++) {
                    wmma::fragment<wmma::matrix_a, 16, 16, 16, __nv_bfloat16, wmma::row_major> af;
                    wmma::load_matrix_sync(af, Ap + (wm * 32 + i * 16) * 72 + ks * 16, 72);
                    wmma::mma_sync(cf[i][0], af, bf[0], cf[i][0]);
                    wmma::mma_sync(cf[i][1], af, bf[1], cf[i][1]);
                }
            }
            __syncthreads();
        }

        #pragma unroll
        for (int i = 0; i < 2; i++)
            #pragma unroll
            for (int j = 0; j < 2; j++)
                wmma::store_matrix_sync(Cs + (wm * 32 + i * 16) * 72 + wn * 32 + j * 16,
                                        cf[i][j], 72, wmma::mem_row_major);
        __syncthreads();

        if (tid < 128) {
            const float* crow = Cs + tid * 72;
            #pragma unroll
            for (int j = 0; j < 64; j++) {
                float key = c2S[j] - 2.f * crow[j];
                ins3(key, t0, t1, t2);
            }
        }
        __syncthreads();
    }

    if (tid < 128) {
        size_t r = (size_t)r0 + tid;
        float f2 = g_feat2[r];
        float d0 = sqrtf(fmaxf(f2 + t0, 0.f));
        float d1 = sqrtf(fmaxf(f2 + t1, 0.f));
        float d2 = sqrtf(fmaxf(f2 + t2, 0.f));
        float s = 1.f / (1.f + expf(d0 - d1) + expf(d0 - d2));
        out[r] = d0 * s;
    }
#endif
}

// ---------------- launch ----------------
extern "C" void kernel_launch(void* const* d_in, const int* in_sizes, int n_in,
                              void* d_out, int out_size) {
    (void)in_sizes; (void)n_in; (void)out_size;
    const float* p0     = (const float*)d_in[0];
    const float* p1     = (const float*)d_in[1];
    const float* p2     = (const float*)d_in[2];
    const float* conv_w = (const float*)d_in[3];
    const float* conv_b = (const float*)d_in[4];
    const float* Cmat   = (const float*)d_in[5];
    float* out = (float*)d_out;

    {
        int t1 = BZ * C1N * 28 * 28;
        pool_kernel<<<(t1 + 255) / 256, 256>>>(p1, t1, 28, 0);
        int t2 = BZ * C2N * 14 * 14;
        pool_kernel<<<(t2 + 255) / 256, 256>>>(p2, t2, 14, 1);
    }
    prepW_kernel<<<(DOUT * KBP + 255) / 256, 256>>>(conv_w);
    prepC_kernel<<<(NC * KCP + 255) / 256, 256>>>(Cmat);
    cent2_kernel<<<(NC * 8 + 255) / 256, 256>>>(Cmat);
    {
        dim3 grid(RR / 64, KBP / 64);
        buildx_kernel<<<grid, 256>>>(p0);
    }
    {
        cudaFuncSetAttribute(gemmB_kernel, cudaFuncAttributeMaxDynamicSharedMemorySize, B_SMEM);
        gemmB_kernel<<<RR / 128, 256, B_SMEM>>>(conv_b);
    }
    {
        cudaFuncSetAttribute(gemmC_kernel, cudaFuncAttributeMaxDynamicSharedMemorySize, C_SMEM);
        gemmC_kernel<<<RR / 128, 256, C_SMEM>>>(out);
    }
}